// round 9
// baseline (speedup 1.0000x reference)
#include <cuda_runtime.h>
#include <cuda_bf16.h>
#include <math.h>
#include <stdint.h>

#define EPS        1e-6f
#define K_COMM     64
#define O_DIM      1024
#define M_TILE     128
#define O_STAGE    64
#define AS_STRIDE  72     // bf16 elements per smem row (padded: conflict-free ldmatrix-free frags)
#define LS_STRIDE  65     // fp32 logits row stride (conflict-free column sweeps)

// Scratch (no allocations allowed): bf16 log-weights + per-tile partial sums.
__device__ __nv_bfloat16 g_logw[K_COMM * O_DIM];
__device__ float         g_partials[1024];

__global__ void prep_logw(const float* __restrict__ otu) {
    int i = blockIdx.x * blockDim.x + threadIdx.x;
    if (i < K_COMM * O_DIM)
        g_logw[i] = __float2bfloat16(logf(otu[i] + EPS));
}

__device__ __forceinline__ uint32_t pack2(float a, float b) {
    __nv_bfloat162 h = __floats2bfloat162_rn(a, b);
    return *reinterpret_cast<uint32_t*>(&h);
}

__device__ __forceinline__ void mma16816(float c[4], const uint32_t a[4], const uint32_t b[2]) {
    asm volatile(
        "mma.sync.aligned.m16n8k16.row.col.f32.bf16.bf16.f32 "
        "{%0,%1,%2,%3}, {%4,%5,%6,%7}, {%8,%9}, {%0,%1,%2,%3};\n"
        : "+f"(c[0]), "+f"(c[1]), "+f"(c[2]), "+f"(c[3])
        : "r"(a[0]), "r"(a[1]), "r"(a[2]), "r"(a[3]),
          "r"(b[0]), "r"(b[1]));
}

// One CTA = 128 rows of counts. 8 warps: warpM in 0..3 (32 rows each), warpN in 0..1 (32 communities).
// Stages O in chunks of 64: counts fp32 -> bf16 into smem, weights bf16 from L2-resident g_logw.
// Fused epilogue: logits -> smem, per-row max-subtracted logsumexp, block-sum -> g_partials.
__global__ __launch_bounds__(256) void gemm_lse(const float* __restrict__ counts,
                                                const float* __restrict__ comm,
                                                int nRows) {
    __shared__ __align__(16) unsigned char smem_raw[M_TILE * LS_STRIDE * 4]; // 33280 B >= As+Bs (27648 B)
    __shared__ float s_prior[K_COMM];
    __shared__ float s_red[256];

    __nv_bfloat16* As = reinterpret_cast<__nv_bfloat16*>(smem_raw);
    __nv_bfloat16* Bs = As + M_TILE * AS_STRIDE;          // byte offset 18432 (16B aligned)
    float*         Ls = reinterpret_cast<float*>(smem_raw); // reused after GEMM

    const int tid     = threadIdx.x;
    const int lane    = tid & 31;
    const int warp    = tid >> 5;
    const int warpM   = warp >> 1;   // 0..3
    const int warpN   = warp & 1;    // 0..1
    const int groupID = lane >> 2;   // 0..7
    const int tig     = lane & 3;    // 0..3

    if (tid < K_COMM) s_prior[tid] = logf(comm[tid] + EPS);

    const int rowBase = blockIdx.x * M_TILE;

    float acc[2][4][4];
#pragma unroll
    for (int mt = 0; mt < 2; ++mt)
#pragma unroll
        for (int nt = 0; nt < 4; ++nt)
#pragma unroll
            for (int i = 0; i < 4; ++i) acc[mt][nt][i] = 0.f;

    // counts-load role: thread t -> row t/2, half t&1 (32 floats = 2x float4 strip)
    const int r    = tid >> 1;
    const int half = tid & 1;
    const int gr   = rowBase + r;
    const bool rowValid = (gr < nRows);
    // weight-load role: thread t -> k row t/4, quarter t&3 (16 bf16 = 2x uint4)
    const int kk = tid >> 2;
    const int q  = tid & 3;

    for (int s = 0; s < O_DIM / O_STAGE; ++s) {
        const int oBase = s * O_STAGE;

        // ---- stage counts tile (fp32 -> bf16) ----
        uint32_t* dstA = reinterpret_cast<uint32_t*>(As + r * AS_STRIDE + half * 32);
        if (rowValid) {
            const float4* src = reinterpret_cast<const float4*>(
                counts + (size_t)gr * O_DIM + oBase + half * 32);
#pragma unroll
            for (int i = 0; i < 8; ++i) {
                float4 v = src[i];
                dstA[2 * i]     = pack2(v.x, v.y);
                dstA[2 * i + 1] = pack2(v.z, v.w);
            }
        } else {
#pragma unroll
            for (int i = 0; i < 16; ++i) dstA[i] = 0u;
        }

        // ---- stage weights tile (bf16, L2-resident) ----
        {
            const uint4* wsrc = reinterpret_cast<const uint4*>(g_logw + kk * O_DIM + oBase + q * 16);
            uint32_t* dstB = reinterpret_cast<uint32_t*>(Bs + kk * AS_STRIDE + q * 16);
            uint4 w0 = wsrc[0];
            uint4 w1 = wsrc[1];
            dstB[0] = w0.x; dstB[1] = w0.y; dstB[2] = w0.z; dstB[3] = w0.w;
            dstB[4] = w1.x; dstB[5] = w1.y; dstB[6] = w1.z; dstB[7] = w1.w;
        }
        __syncthreads();

        // ---- MMA over this stage: 4 k-chunks of 16 ----
#pragma unroll
        for (int oc = 0; oc < O_STAGE; oc += 16) {
            uint32_t a[2][4];
#pragma unroll
            for (int mt = 0; mt < 2; ++mt) {
                const int row0 = warpM * 32 + mt * 16 + groupID;
                const __nv_bfloat16* p = As + row0 * AS_STRIDE + oc + 2 * tig;
                a[mt][0] = *reinterpret_cast<const uint32_t*>(p);
                a[mt][1] = *reinterpret_cast<const uint32_t*>(p + 8 * AS_STRIDE);
                a[mt][2] = *reinterpret_cast<const uint32_t*>(p + 8);
                a[mt][3] = *reinterpret_cast<const uint32_t*>(p + 8 * AS_STRIDE + 8);
            }
            uint32_t b[4][2];
#pragma unroll
            for (int nt = 0; nt < 4; ++nt) {
                const int k0 = warpN * 32 + nt * 8 + groupID;
                const __nv_bfloat16* p = Bs + k0 * AS_STRIDE + oc + 2 * tig;
                b[nt][0] = *reinterpret_cast<const uint32_t*>(p);
                b[nt][1] = *reinterpret_cast<const uint32_t*>(p + 8);
            }
#pragma unroll
            for (int mt = 0; mt < 2; ++mt)
#pragma unroll
                for (int nt = 0; nt < 4; ++nt)
                    mma16816(acc[mt][nt], a[mt], b[nt]);
        }
        __syncthreads();
    }

    // ---- spill logits to smem (C-frag layout -> row-major [128][64], stride 65) ----
#pragma unroll
    for (int mt = 0; mt < 2; ++mt) {
        const int r0 = warpM * 32 + mt * 16 + groupID;
#pragma unroll
        for (int nt = 0; nt < 4; ++nt) {
            const int c0 = warpN * 32 + nt * 8 + 2 * tig;
            Ls[r0 * LS_STRIDE + c0]           = acc[mt][nt][0];
            Ls[r0 * LS_STRIDE + c0 + 1]       = acc[mt][nt][1];
            Ls[(r0 + 8) * LS_STRIDE + c0]     = acc[mt][nt][2];
            Ls[(r0 + 8) * LS_STRIDE + c0 + 1] = acc[mt][nt][3];
        }
    }
    __syncthreads();

    // ---- per-row logsumexp (threads 0..127 each own one row) ----
    float val = 0.f;
    if (tid < M_TILE) {
        const int grr = rowBase + tid;
        if (grr < nRows) {
            float m = -INFINITY;
#pragma unroll
            for (int k = 0; k < K_COMM; ++k) {
                float x = Ls[tid * LS_STRIDE + k] + s_prior[k];
                Ls[tid * LS_STRIDE + k] = x;
                m = fmaxf(m, x);
            }
            float ssum = 0.f;
#pragma unroll
            for (int k = 0; k < K_COMM; ++k)
                ssum += expf(Ls[tid * LS_STRIDE + k] - m);
            val = m + logf(ssum);
        }
    }
    s_red[tid] = val;
    __syncthreads();
#pragma unroll
    for (int off = 128; off > 0; off >>= 1) {
        if (tid < off) s_red[tid] += s_red[tid + off];
        __syncthreads();
    }
    if (tid == 0) g_partials[blockIdx.x] = s_red[0];
}

__global__ void final_reduce(float* __restrict__ out, int nTiles) {
    __shared__ double sred[256];
    double s = 0.0;
    for (int i = threadIdx.x; i < nTiles; i += 256) s += (double)g_partials[i];
    sred[threadIdx.x] = s;
    __syncthreads();
#pragma unroll
    for (int off = 128; off > 0; off >>= 1) {
        if (threadIdx.x < off) sred[threadIdx.x] += sred[threadIdx.x + off];
        __syncthreads();
    }
    if (threadIdx.x == 0) out[0] = (float)sred[0];
}

extern "C" void kernel_launch(void* const* d_in, const int* in_sizes, int n_in,
                              void* d_out, int out_size) {
    const float* counts = (const float*)d_in[0];   // (N, 1024) fp32
    const float* otu    = (const float*)d_in[1];   // (64, 1024) fp32
    const float* comm   = (const float*)d_in[2];   // (64,) fp32
    float* out = (float*)d_out;                    // scalar fp32

    const int nRows  = in_sizes[0] / O_DIM;
    const int nTiles = (nRows + M_TILE - 1) / M_TILE;

    prep_logw<<<(K_COMM * O_DIM + 255) / 256, 256>>>(otu);
    gemm_lse<<<nTiles, 256>>>(counts, comm, nRows);
    final_reduce<<<1, 256>>>(out, nTiles);
}

// round 10
// speedup vs baseline: 1.0728x; 1.0728x over previous
#include <cuda_runtime.h>
#include <cuda_bf16.h>
#include <math.h>
#include <stdint.h>

#define EPS        1e-6f
#define K_COMM     64
#define O_DIM      1024
#define M_TILE     128
#define O_STAGE    64
#define N_STAGES   (O_DIM / O_STAGE)
#define AS_STRIDE  72     // bf16 elems per smem row (144B rows: 16B-aligned, conflict-spread)
#define LS_STRIDE  65     // fp32 logits row stride

// Scratch (no allocations allowed): bf16 log-weights + per-tile partial sums.
__device__ __nv_bfloat16 g_logw[K_COMM * O_DIM];
__device__ float         g_partials[1024];

__global__ void prep_logw(const float* __restrict__ otu) {
    int i = blockIdx.x * blockDim.x + threadIdx.x;
    if (i < K_COMM * O_DIM)
        g_logw[i] = __float2bfloat16(logf(otu[i] + EPS));
}

__device__ __forceinline__ uint32_t pack2(float a, float b) {
    __nv_bfloat162 h = __floats2bfloat162_rn(a, b);
    return *reinterpret_cast<uint32_t*>(&h);
}

__device__ __forceinline__ void mma16816(float c[4], const uint32_t a[4], const uint32_t b[2]) {
    asm volatile(
        "mma.sync.aligned.m16n8k16.row.col.f32.bf16.bf16.f32 "
        "{%0,%1,%2,%3}, {%4,%5,%6,%7}, {%8,%9}, {%0,%1,%2,%3};\n"
        : "+f"(c[0]), "+f"(c[1]), "+f"(c[2]), "+f"(c[3])
        : "r"(a[0]), "r"(a[1]), "r"(a[2]), "r"(a[3]),
          "r"(b[0]), "r"(b[1]));
}

// Per-thread prefetch of one A stage (32 floats -> 16 packed bf16x2 regs).
__device__ __forceinline__ void loadA(uint32_t aReg[16], const float* __restrict__ src, bool valid) {
    if (valid) {
        const float4* s4 = reinterpret_cast<const float4*>(src);
#pragma unroll
        for (int i = 0; i < 8; ++i) {
            float4 v = s4[i];
            aReg[2 * i]     = pack2(v.x, v.y);
            aReg[2 * i + 1] = pack2(v.z, v.w);
        }
    } else {
#pragma unroll
        for (int i = 0; i < 16; ++i) aReg[i] = 0u;
    }
}

__device__ __forceinline__ void loadB(uint4 bReg[2], const __nv_bfloat16* __restrict__ src) {
    const uint4* s = reinterpret_cast<const uint4*>(src);
    bReg[0] = s[0];
    bReg[1] = s[1];
}

// One CTA = 128 rows. 8 warps: warpM 0..3 (32 rows), warpN 0..1 (32 communities).
// Software-pipelined: regs prefetch stage s+1 while MMA consumes double-buffered smem stage s.
__global__ __launch_bounds__(256) void gemm_lse(const float* __restrict__ counts,
                                                const float* __restrict__ comm,
                                                int nRows) {
    // Double-buffered A (2 x 128x72 bf16) + B (2 x 64x72 bf16) = 55296 B.
    __shared__ __align__(16) __nv_bfloat16 smem[2 * M_TILE * AS_STRIDE + 2 * K_COMM * AS_STRIDE];
    __shared__ float s_prior[K_COMM];
    __shared__ float s_red[256];

    float* Ls = reinterpret_cast<float*>(smem);  // epilogue reuse (33280 B <= 55296 B)

    const int tid     = threadIdx.x;
    const int lane    = tid & 31;
    const int warp    = tid >> 5;
    const int warpM   = warp >> 1;
    const int warpN   = warp & 1;
    const int groupID = lane >> 2;
    const int tig     = lane & 3;

    if (tid < K_COMM) s_prior[tid] = logf(comm[tid] + EPS);

    const int rowBase = blockIdx.x * M_TILE;

    float acc[2][4][4];
#pragma unroll
    for (int mt = 0; mt < 2; ++mt)
#pragma unroll
        for (int nt = 0; nt < 4; ++nt)
#pragma unroll
            for (int i = 0; i < 4; ++i) acc[mt][nt][i] = 0.f;

    // A-staging role: thread t -> row t/2, half t&1 (32 floats).
    const int r    = tid >> 1;
    const int half = tid & 1;
    const int gr   = rowBase + r;
    const bool rowValid = (gr < nRows);
    // B-staging role: thread t -> k row t/4, quarter t&3 (16 bf16).
    const int kk = tid >> 2;
    const int q  = tid & 3;

    const float* aSrc = counts + (size_t)gr * O_DIM + half * 32;
    const __nv_bfloat16* bSrc = g_logw + kk * O_DIM + q * 16;

    uint32_t aReg[16];
    uint4    bReg[2];
    loadA(aReg, aSrc, rowValid);
    loadB(bReg, bSrc);

#pragma unroll 2
    for (int s = 0; s < N_STAGES; ++s) {
        __nv_bfloat16* As = smem + (s & 1) * (M_TILE * AS_STRIDE);
        __nv_bfloat16* Bs = smem + 2 * M_TILE * AS_STRIDE + (s & 1) * (K_COMM * AS_STRIDE);

        // ---- commit staged regs to smem ----
        {
            uint2* dA = reinterpret_cast<uint2*>(As + r * AS_STRIDE + half * 32);
#pragma unroll
            for (int i = 0; i < 8; ++i)
                dA[i] = make_uint2(aReg[2 * i], aReg[2 * i + 1]);
            uint4* dB = reinterpret_cast<uint4*>(Bs + kk * AS_STRIDE + q * 16);
            dB[0] = bReg[0];
            dB[1] = bReg[1];
        }
        __syncthreads();

        // ---- prefetch next stage (latency hidden behind MMA below) ----
        if (s + 1 < N_STAGES) {
            loadA(aReg, aSrc + (s + 1) * O_STAGE, rowValid);
            loadB(bReg, bSrc + (s + 1) * O_STAGE);
        }

        // ---- MMA over this stage: 4 k-chunks of 16 ----
#pragma unroll
        for (int oc = 0; oc < O_STAGE; oc += 16) {
            uint32_t a[2][4];
#pragma unroll
            for (int mt = 0; mt < 2; ++mt) {
                const int row0 = warpM * 32 + mt * 16 + groupID;
                const __nv_bfloat16* p = As + row0 * AS_STRIDE + oc + 2 * tig;
                a[mt][0] = *reinterpret_cast<const uint32_t*>(p);
                a[mt][1] = *reinterpret_cast<const uint32_t*>(p + 8 * AS_STRIDE);
                a[mt][2] = *reinterpret_cast<const uint32_t*>(p + 8);
                a[mt][3] = *reinterpret_cast<const uint32_t*>(p + 8 * AS_STRIDE + 8);
            }
            uint32_t b[4][2];
#pragma unroll
            for (int nt = 0; nt < 4; ++nt) {
                const int k0 = warpN * 32 + nt * 8 + groupID;
                const __nv_bfloat16* p = Bs + k0 * AS_STRIDE + oc + 2 * tig;
                b[nt][0] = *reinterpret_cast<const uint32_t*>(p);
                b[nt][1] = *reinterpret_cast<const uint32_t*>(p + 8);
            }
#pragma unroll
            for (int mt = 0; mt < 2; ++mt)
#pragma unroll
                for (int nt = 0; nt < 4; ++nt)
                    mma16816(acc[mt][nt], a[mt], b[nt]);
        }
        // No trailing sync: next iteration writes the OTHER buffer; its
        // __syncthreads (after STS) orders all warps past this MMA before
        // this buffer is overwritten two stages later.
    }
    __syncthreads();  // all MMA reads done before Ls aliases the buffers

    // ---- spill logits to smem (C-frag layout -> row-major [128][64], stride 65) ----
#pragma unroll
    for (int mt = 0; mt < 2; ++mt) {
        const int r0 = warpM * 32 + mt * 16 + groupID;
#pragma unroll
        for (int nt = 0; nt < 4; ++nt) {
            const int c0 = warpN * 32 + nt * 8 + 2 * tig;
            Ls[r0 * LS_STRIDE + c0]           = acc[mt][nt][0];
            Ls[r0 * LS_STRIDE + c0 + 1]       = acc[mt][nt][1];
            Ls[(r0 + 8) * LS_STRIDE + c0]     = acc[mt][nt][2];
            Ls[(r0 + 8) * LS_STRIDE + c0 + 1] = acc[mt][nt][3];
        }
    }
    __syncthreads();

    // ---- per-row logsumexp: 2 threads per row (tid^1 pairs), shfl-combined ----
    float val = 0.f;
    {
        const int row = tid >> 1;
        const int kh  = (tid & 1) * 32;
        const int grr = rowBase + row;
        float m = -INFINITY;
#pragma unroll
        for (int k = 0; k < 32; ++k) {
            float x = Ls[row * LS_STRIDE + kh + k] + s_prior[kh + k];
            Ls[row * LS_STRIDE + kh + k] = x;
            m = fmaxf(m, x);
        }
        const float mo = __shfl_xor_sync(0xffffffffu, m, 1);
        const float mm = fmaxf(m, mo);
        float ssum = 0.f;
#pragma unroll
        for (int k = 0; k < 32; ++k)
            ssum += __expf(Ls[row * LS_STRIDE + kh + k] - mm);
        const float so = __shfl_xor_sync(0xffffffffu, ssum, 1);
        if ((tid & 1) == 0 && grr < nRows)
            val = mm + __logf(ssum + so);
    }
    s_red[tid] = val;
    __syncthreads();
#pragma unroll
    for (int off = 128; off > 0; off >>= 1) {
        if (tid < off) s_red[tid] += s_red[tid + off];
        __syncthreads();
    }
    if (tid == 0) g_partials[blockIdx.x] = s_red[0];
}

__global__ void final_reduce(float* __restrict__ out, int nTiles) {
    __shared__ double sred[256];
    double s = 0.0;
    for (int i = threadIdx.x; i < nTiles; i += 256) s += (double)g_partials[i];
    sred[threadIdx.x] = s;
    __syncthreads();
#pragma unroll
    for (int off = 128; off > 0; off >>= 1) {
        if (threadIdx.x < off) sred[threadIdx.x] += sred[threadIdx.x + off];
        __syncthreads();
    }
    if (threadIdx.x == 0) out[0] = (float)sred[0];
}

extern "C" void kernel_launch(void* const* d_in, const int* in_sizes, int n_in,
                              void* d_out, int out_size) {
    const float* counts = (const float*)d_in[0];   // (N, 1024) fp32
    const float* otu    = (const float*)d_in[1];   // (64, 1024) fp32
    const float* comm   = (const float*)d_in[2];   // (64,) fp32
    float* out = (float*)d_out;                    // scalar fp32

    const int nRows  = in_sizes[0] / O_DIM;
    const int nTiles = (nRows + M_TILE - 1) / M_TILE;

    prep_logw<<<(K_COMM * O_DIM + 255) / 256, 256>>>(otu);
    gemm_lse<<<nTiles, 256>>>(counts, comm, nRows);
    final_reduce<<<1, 256>>>(out, nTiles);
}

// round 11
// speedup vs baseline: 1.1236x; 1.0473x over previous
#include <cuda_runtime.h>
#include <cuda_bf16.h>
#include <math.h>
#include <stdint.h>

#define EPS        1e-6f
#define K_COMM     64
#define O_DIM      1024
#define M_TILE     128
#define O_STAGE    32
#define NSTAGE     (O_DIM / O_STAGE)   // 32
#define PIPE       4
#define AS_F       36                  // fp32 elems per smem row (144B: frag LDS conflict-free)
#define A_STAGE_F  (M_TILE * AS_F)     // 4608 floats (18432 B)
#define B_STAGE_F  (K_COMM * AS_F)     // 2304 floats (9216 B)
#define SMEM_FLOATS (PIPE * A_STAGE_F + PIPE * B_STAGE_F + K_COMM + 256)
#define SMEM_BYTES  (SMEM_FLOATS * 4)  // 111872 B
#define LS_STRIDE  65

// Scratch: tf32-rounded log-weights (fp32 container) + per-tile partials.
__device__ float g_logw[K_COMM * O_DIM];
__device__ float g_partials[1024];

__global__ void prep_logw(const float* __restrict__ otu) {
    int i = blockIdx.x * blockDim.x + threadIdx.x;
    if (i < K_COMM * O_DIM) {
        float v = logf(otu[i] + EPS);
        uint32_t u;
        asm("cvt.rna.tf32.f32 %0, %1;" : "=r"(u) : "f"(v));
        g_logw[i] = __uint_as_float(u);
    }
}

__device__ __forceinline__ void cp16(uint32_t dst, const void* src, int srcBytes) {
    asm volatile("cp.async.cg.shared.global [%0], [%1], 16, %2;\n"
                 :: "r"(dst), "l"(src), "r"(srcBytes));
}
__device__ __forceinline__ void cp_commit() {
    asm volatile("cp.async.commit_group;\n");
}
__device__ __forceinline__ void cp_wait() {   // all but last PIPE-2 groups
    asm volatile("cp.async.wait_group %0;\n" :: "n"(PIPE - 2));
}

__device__ __forceinline__ void mma_tf32(float c[4], const uint32_t a[4], const uint32_t b[2]) {
    asm volatile(
        "mma.sync.aligned.m16n8k8.row.col.f32.tf32.tf32.f32 "
        "{%0,%1,%2,%3}, {%4,%5,%6,%7}, {%8,%9}, {%0,%1,%2,%3};\n"
        : "+f"(c[0]), "+f"(c[1]), "+f"(c[2]), "+f"(c[3])
        : "r"(a[0]), "r"(a[1]), "r"(a[2]), "r"(a[3]),
          "r"(b[0]), "r"(b[1]));
}

// One CTA = 128 rows. 8 warps: warpM 0..3 (32 rows), warpN 0..1 (32 communities).
// 4-deep cp.async pipeline: GMEM -> SMEM with zero register involvement;
// tf32 MMA consumes fp32 counts directly (exact for integer counts 0..9).
__global__ __launch_bounds__(256, 2) void gemm_lse(const float* __restrict__ counts,
                                                   const float* __restrict__ comm,
                                                   int nRows) {
    extern __shared__ __align__(16) float dyn[];
    float* s_prior = dyn + PIPE * A_STAGE_F + PIPE * B_STAGE_F;
    float* s_red   = s_prior + K_COMM;
    float* Ls      = dyn;   // epilogue reuse (8320 floats < A-stage region 18432)

    const int tid     = threadIdx.x;
    const int lane    = tid & 31;
    const int warp    = tid >> 5;
    const int warpM   = warp >> 1;
    const int warpN   = warp & 1;
    const int g       = lane >> 2;   // groupID 0..7
    const int t       = lane & 3;    // 0..3

    if (tid < K_COMM) s_prior[tid] = logf(comm[tid] + EPS);

    const int rowBase = blockIdx.x * M_TILE;

    float acc[2][4][4];
#pragma unroll
    for (int mt = 0; mt < 2; ++mt)
#pragma unroll
        for (int nt = 0; nt < 4; ++nt)
#pragma unroll
            for (int i = 0; i < 4; ++i) acc[mt][nt][i] = 0.f;

    // A-staging role: thread -> row tid/2, half tid&1 (16 floats = 4x 16B).
    const int r    = tid >> 1;
    const int half = tid & 1;
    const int gr   = rowBase + r;
    const int aSz  = (gr < nRows) ? 16 : 0;              // zfill OOB rows
    const int grc  = (gr < nRows) ? gr : (nRows - 1);    // keep address valid
    const float* aSrc = counts + (size_t)grc * O_DIM + half * 16;
    const uint32_t dA0 = (uint32_t)__cvta_generic_to_shared(dyn) +
                         (uint32_t)((r * AS_F + half * 16) * 4);
    // B-staging role: thread -> k-row tid/4, quarter tid&3 (8 floats = 2x 16B).
    const int kk = tid >> 2;
    const int q  = tid & 3;
    const float* bSrc = g_logw + kk * O_DIM + q * 8;
    const uint32_t dB0 = (uint32_t)__cvta_generic_to_shared(dyn + PIPE * A_STAGE_F) +
                         (uint32_t)((kk * AS_F + q * 8) * 4);

    auto issue = [&](int s) {
        const uint32_t dA = dA0 + (uint32_t)((s & (PIPE - 1)) * A_STAGE_F * 4);
        const float* sA = aSrc + s * O_STAGE;
#pragma unroll
        for (int i = 0; i < 4; ++i)
            cp16(dA + i * 16, sA + i * 4, aSz);
        const uint32_t dB = dB0 + (uint32_t)((s & (PIPE - 1)) * B_STAGE_F * 4);
        const float* sB = bSrc + s * O_STAGE;
#pragma unroll
        for (int i = 0; i < 2; ++i)
            cp16(dB + i * 16, sB + i * 4, 16);
    };

    // Prologue: fill PIPE-1 stages.
#pragma unroll
    for (int ps = 0; ps < PIPE - 1; ++ps) {
        issue(ps);
        cp_commit();
    }

    for (int s = 0; s < NSTAGE; ++s) {
        cp_wait();            // stage s landed
        __syncthreads();      // visible to all; all warps past stage s-1 reads

        // Refill buffer (s-1)&3 with stage s+PIPE-1 (safe: barrier above).
        if (s + PIPE - 1 < NSTAGE) issue(s + PIPE - 1);
        cp_commit();          // commit every iteration (possibly empty group)

        const float* As = dyn + (s & (PIPE - 1)) * A_STAGE_F;
        const float* Bs = dyn + PIPE * A_STAGE_F + (s & (PIPE - 1)) * B_STAGE_F;

#pragma unroll
        for (int oc = 0; oc < O_STAGE; oc += 8) {
            uint32_t a[2][4];
#pragma unroll
            for (int mt = 0; mt < 2; ++mt) {
                const float* p = As + (warpM * 32 + mt * 16 + g) * AS_F + oc + t;
                a[mt][0] = __float_as_uint(p[0]);
                a[mt][1] = __float_as_uint(p[8 * AS_F]);
                a[mt][2] = __float_as_uint(p[4]);
                a[mt][3] = __float_as_uint(p[8 * AS_F + 4]);
            }
            uint32_t b[4][2];
#pragma unroll
            for (int nt = 0; nt < 4; ++nt) {
                const float* p = Bs + (warpN * 32 + nt * 8 + g) * AS_F + oc + t;
                b[nt][0] = __float_as_uint(p[0]);
                b[nt][1] = __float_as_uint(p[4]);
            }
#pragma unroll
            for (int mt = 0; mt < 2; ++mt)
#pragma unroll
                for (int nt = 0; nt < 4; ++nt)
                    mma_tf32(acc[mt][nt], a[mt], b[nt]);
        }
    }
    __syncthreads();   // all MMA reads done before Ls aliases the buffers

    // ---- spill logits (C-frag -> row-major [128][64], stride 65) ----
#pragma unroll
    for (int mt = 0; mt < 2; ++mt) {
        const int r0 = warpM * 32 + mt * 16 + g;
#pragma unroll
        for (int nt = 0; nt < 4; ++nt) {
            const int c0 = warpN * 32 + nt * 8 + 2 * t;
            Ls[r0 * LS_STRIDE + c0]           = acc[mt][nt][0];
            Ls[r0 * LS_STRIDE + c0 + 1]       = acc[mt][nt][1];
            Ls[(r0 + 8) * LS_STRIDE + c0]     = acc[mt][nt][2];
            Ls[(r0 + 8) * LS_STRIDE + c0 + 1] = acc[mt][nt][3];
        }
    }
    __syncthreads();

    // ---- per-row logsumexp: 2 threads per row, shfl-combined ----
    float val = 0.f;
    {
        const int row = tid >> 1;
        const int kh  = (tid & 1) * 32;
        const int grr = rowBase + row;
        float m = -INFINITY;
#pragma unroll
        for (int k = 0; k < 32; ++k) {
            float x = Ls[row * LS_STRIDE + kh + k] + s_prior[kh + k];
            Ls[row * LS_STRIDE + kh + k] = x;
            m = fmaxf(m, x);
        }
        const float mo = __shfl_xor_sync(0xffffffffu, m, 1);
        const float mm = fmaxf(m, mo);
        float ssum = 0.f;
#pragma unroll
        for (int k = 0; k < 32; ++k)
            ssum += __expf(Ls[row * LS_STRIDE + kh + k] - mm);
        const float so = __shfl_xor_sync(0xffffffffu, ssum, 1);
        if ((tid & 1) == 0 && grr < nRows)
            val = mm + __logf(ssum + so);
    }
    s_red[tid] = val;
    __syncthreads();
#pragma unroll
    for (int off = 128; off > 0; off >>= 1) {
        if (tid < off) s_red[tid] += s_red[tid + off];
        __syncthreads();
    }
    if (tid == 0) g_partials[blockIdx.x] = s_red[0];
}

__global__ void final_reduce(float* __restrict__ out, int nTiles) {
    __shared__ double sred[256];
    double s = 0.0;
    for (int i = threadIdx.x; i < nTiles; i += 256) s += (double)g_partials[i];
    sred[threadIdx.x] = s;
    __syncthreads();
#pragma unroll
    for (int off = 128; off > 0; off >>= 1) {
        if (threadIdx.x < off) sred[threadIdx.x] += sred[threadIdx.x + off];
        __syncthreads();
    }
    if (threadIdx.x == 0) out[0] = (float)sred[0];
}

extern "C" void kernel_launch(void* const* d_in, const int* in_sizes, int n_in,
                              void* d_out, int out_size) {
    const float* counts = (const float*)d_in[0];   // (N, 1024) fp32
    const float* otu    = (const float*)d_in[1];   // (64, 1024) fp32
    const float* comm   = (const float*)d_in[2];   // (64,) fp32
    float* out = (float*)d_out;                    // scalar fp32

    const int nRows  = in_sizes[0] / O_DIM;
    const int nTiles = (nRows + M_TILE - 1) / M_TILE;

    static bool smem_set = false;  // idempotent attribute, safe under capture
    if (!smem_set) {
        cudaFuncSetAttribute(gemm_lse, cudaFuncAttributeMaxDynamicSharedMemorySize,
                             SMEM_BYTES);
        smem_set = true;
    }

    prep_logw<<<(K_COMM * O_DIM + 255) / 256, 256>>>(otu);
    gemm_lse<<<nTiles, 256, SMEM_BYTES>>>(counts, comm, nRows);
    final_reduce<<<1, 256>>>(out, nTiles);
}